// round 2
// baseline (speedup 1.0000x reference)
#include <cuda_runtime.h>
#include <cuda_bf16.h>
#include <math.h>

#define NODES 100000
#define EDGES 1600000
#define DIMS  64
#define H2    128
#define NGRAPH 512
#define NLAYER 4
#define BN_EPS 1e-5f

#define SCAN_B 1024
#define SCAN_NB ((NODES + SCAN_B - 1) / SCAN_B)   // 98

// ---------------- device scratch (static; no allocations allowed) -------------
__device__ int   g_is64;
__device__ int   g_srcI[EDGES];
__device__ int   g_dstI[EDGES];
__device__ int   g_batI[NODES];

__device__ int   g_deg[NODES];
__device__ int   g_rowstart[NODES + 1];
__device__ int   g_cursor[NODES];
__device__ int   g_srcsorted[EDGES];
__device__ int   g_bsum[256];

__device__ float g_h[NODES * DIMS];   // current node features
__device__ float g_z[NODES * DIMS];   // h + aggregated neighbors
__device__ float g_t[NODES * H2];     // hidden (after first linear)

__device__ float g_alpha1[NLAYER][H2], g_beta1[NLAYER][H2];
__device__ float g_alpha2[NLAYER][DIMS], g_beta2[NLAYER][DIMS];

// ---------------- index dtype detection + conversion --------------------------
__global__ void probe_kernel(const int* __restrict__ ei_raw) {
    // int64 little-endian values < 2^17: every odd int32 word is 0.
    int odd_nonzero = 0;
    #pragma unroll
    for (int t = 1; t < 32; t += 2) odd_nonzero |= (ei_raw[t] != 0);
    g_is64 = odd_nonzero ? 0 : 1;
}

__device__ __forceinline__ int clampN(int v) {
    return v < 0 ? 0 : (v >= NODES ? NODES - 1 : v);
}

__global__ void conv_edges_kernel(const void* __restrict__ ei) {
    int e = blockIdx.x * blockDim.x + threadIdx.x;
    if (e >= EDGES) return;
    int s, d;
    if (g_is64) {
        const long long* p = (const long long*)ei;
        s = (int)p[e];
        d = (int)p[EDGES + e];
    } else {
        const int* p = (const int*)ei;
        s = p[e];
        d = p[EDGES + e];
    }
    s = clampN(s); d = clampN(d);
    g_srcI[e] = s;
    g_dstI[e] = d;
    atomicAdd(&g_deg[d], 1);
}

__global__ void conv_batch_kernel(const void* __restrict__ bat) {
    int i = blockIdx.x * blockDim.x + threadIdx.x;
    if (i >= NODES) return;
    int b;
    if (g_is64) b = (int)((const long long*)bat)[i];
    else        b = ((const int*)bat)[i];
    g_batI[i] = b < 0 ? 0 : (b >= NGRAPH ? NGRAPH - 1 : b);
}

// ---------------- small utility kernels --------------------------------------
__global__ void copy_x_kernel(const float4* __restrict__ x) {
    int i = blockIdx.x * blockDim.x + threadIdx.x;
    if (i < NODES * (DIMS / 4)) ((float4*)g_h)[i] = x[i];
}

__global__ void zero_deg_kernel() {
    int i = blockIdx.x * blockDim.x + threadIdx.x;
    if (i < NODES) g_deg[i] = 0;
}

// per-block exclusive scan + block sums
__global__ void scan1_kernel() {
    __shared__ int sh[SCAN_B];
    int i = blockIdx.x * SCAN_B + threadIdx.x;
    int v = (i < NODES) ? g_deg[i] : 0;
    sh[threadIdx.x] = v;
    __syncthreads();
    for (int off = 1; off < SCAN_B; off <<= 1) {
        int t = (threadIdx.x >= off) ? sh[threadIdx.x - off] : 0;
        __syncthreads();
        sh[threadIdx.x] += t;
        __syncthreads();
    }
    if (i < NODES) g_rowstart[i] = sh[threadIdx.x] - v;     // exclusive
    if (threadIdx.x == SCAN_B - 1) g_bsum[blockIdx.x] = sh[SCAN_B - 1];
}

__global__ void scan2_kernel() {
    __shared__ int sh[128];
    int v = (threadIdx.x < SCAN_NB) ? g_bsum[threadIdx.x] : 0;
    sh[threadIdx.x] = v;
    __syncthreads();
    for (int off = 1; off < 128; off <<= 1) {
        int t = (threadIdx.x >= off) ? sh[threadIdx.x - off] : 0;
        __syncthreads();
        sh[threadIdx.x] += t;
        __syncthreads();
    }
    if (threadIdx.x < SCAN_NB) g_bsum[threadIdx.x] = sh[threadIdx.x] - v; // exclusive
}

__global__ void scan3_kernel() {
    int i = blockIdx.x * blockDim.x + threadIdx.x;
    if (i < NODES) {
        int r = g_rowstart[i] + g_bsum[i / SCAN_B];
        g_rowstart[i] = r;
        g_cursor[i] = r;
    }
    if (i == 0) g_rowstart[NODES] = EDGES;
}

__global__ void fill_kernel() {
    int e = blockIdx.x * blockDim.x + threadIdx.x;
    if (e < EDGES) {
        int d = g_dstI[e];
        int p = atomicAdd(&g_cursor[d], 1);
        g_srcsorted[p] = g_srcI[e];
    }
}

// fold BN (+ bias) into per-column alpha/beta once
__global__ void prep_kernel(const float* __restrict__ b1, const float* __restrict__ g1,
                            const float* __restrict__ bt1, const float* __restrict__ m1,
                            const float* __restrict__ v1,
                            const float* __restrict__ b2, const float* __restrict__ g2,
                            const float* __restrict__ bt2, const float* __restrict__ m2,
                            const float* __restrict__ v2) {
    int l = blockIdx.x;
    int c = threadIdx.x;
    if (c < H2) {
        int i = l * H2 + c;
        float s = g1[i] * rsqrtf(v1[i] + BN_EPS);
        g_alpha1[l][c] = s;
        g_beta1[l][c]  = (b1[i] - m1[i]) * s + bt1[i];
    }
    if (c < DIMS) {
        int i = l * DIMS + c;
        float s = g2[i] * rsqrtf(v2[i] + BN_EPS);
        g_alpha2[l][c] = s;
        g_beta2[l][c]  = (b2[i] - m2[i]) * s + bt2[i];
    }
}

// ---------------- aggregation: warp per node, CSR gather ----------------------
__global__ void agg_kernel() {
    int warp = (blockIdx.x * blockDim.x + threadIdx.x) >> 5;
    int lane = threadIdx.x & 31;
    if (warp >= NODES) return;
    int rs = g_rowstart[warp];
    int re = g_rowstart[warp + 1];
    const float2* __restrict__ h2 = (const float2*)g_h;
    float2 acc = h2[warp * 32 + lane];      // z = h + agg
    for (int base = rs; base < re; base += 32) {
        int n = re - base; if (n > 32) n = 32;
        int s = 0;
        if (base + lane < re) s = g_srcsorted[base + lane];
        #pragma unroll 4
        for (int t = 0; t < n; t++) {
            int ss = __shfl_sync(0xffffffffu, s, t);
            float2 v = h2[ss * 32 + lane];
            acc.x += v.x;
            acc.y += v.y;
        }
    }
    ((float2*)g_z)[warp * 32 + lane] = acc;
}

// ---------------- GEMM1: [N,64] @ [64,128], fused BN+ReLU -> g_t --------------
// tile 64 nodes x 128 cols, 256 threads, thread tile 4x8
#define AS1 76   // padded A stride
__global__ void __launch_bounds__(256) gemm1_kernel(const float* __restrict__ W1, int layer) {
    extern __shared__ float sm[];
    float* As = sm;                 // [64][AS1]
    float* Ws = sm + 64 * AS1;      // [64][128]
    const float* __restrict__ W = W1 + layer * DIMS * H2;
    int m0 = blockIdx.x * 64;
    int tid = threadIdx.x;

    for (int i = tid; i < 64 * 64; i += 256) {
        int r = i >> 6, c = i & 63;
        int node = m0 + r;
        As[r * AS1 + c] = (node < NODES) ? g_z[node * DIMS + c] : 0.f;
    }
    for (int i = tid; i < 64 * 128; i += 256) Ws[i] = W[i];
    __syncthreads();

    int cg = tid & 15, ng = tid >> 4;
    int c0 = cg * 8, n0 = ng * 4;
    float acc[4][8];
    #pragma unroll
    for (int j = 0; j < 4; j++)
        #pragma unroll
        for (int cc = 0; cc < 8; cc++) acc[j][cc] = 0.f;

    #pragma unroll 2
    for (int k = 0; k < 64; k += 4) {
        float a[4][4];
        #pragma unroll
        for (int j = 0; j < 4; j++)
            *(float4*)a[j] = *(const float4*)&As[(n0 + j) * AS1 + k];
        #pragma unroll
        for (int kk = 0; kk < 4; kk++) {
            float4 b0 = *(const float4*)&Ws[(k + kk) * 128 + c0];
            float4 b1 = *(const float4*)&Ws[(k + kk) * 128 + c0 + 4];
            float bb[8] = {b0.x, b0.y, b0.z, b0.w, b1.x, b1.y, b1.z, b1.w};
            #pragma unroll
            for (int j = 0; j < 4; j++) {
                float av = a[j][kk];
                #pragma unroll
                for (int cc = 0; cc < 8; cc++)
                    acc[j][cc] = fmaf(av, bb[cc], acc[j][cc]);
            }
        }
    }

    float al[8], be[8];
    #pragma unroll
    for (int cc = 0; cc < 8; cc++) {
        al[cc] = g_alpha1[layer][c0 + cc];
        be[cc] = g_beta1[layer][c0 + cc];
    }
    #pragma unroll
    for (int j = 0; j < 4; j++) {
        int node = m0 + n0 + j;
        if (node < NODES) {
            float o[8];
            #pragma unroll
            for (int cc = 0; cc < 8; cc++)
                o[cc] = fmaxf(fmaf(acc[j][cc], al[cc], be[cc]), 0.f);
            *(float4*)&g_t[node * H2 + c0]     = make_float4(o[0], o[1], o[2], o[3]);
            *(float4*)&g_t[node * H2 + c0 + 4] = make_float4(o[4], o[5], o[6], o[7]);
        }
    }
}

// ---------------- GEMM2: [N,128] @ [128,64], fused BN(+ReLU) -> g_h -----------
// tile 64 nodes x 64 cols, 256 threads, thread tile 4x4
#define AS2 140  // padded A stride (K=128)
__global__ void __launch_bounds__(256) gemm2_kernel(const float* __restrict__ W2, int layer, int relu) {
    extern __shared__ float sm[];
    float* As = sm;                 // [64][AS2]
    float* Ws = sm + 64 * AS2;      // [128][64]
    const float* __restrict__ W = W2 + layer * H2 * DIMS;
    int m0 = blockIdx.x * 64;
    int tid = threadIdx.x;

    for (int i = tid; i < 64 * 128; i += 256) {
        int r = i >> 7, c = i & 127;
        int node = m0 + r;
        As[r * AS2 + c] = (node < NODES) ? g_t[node * H2 + c] : 0.f;
    }
    for (int i = tid; i < 128 * 64; i += 256) Ws[i] = W[i];
    __syncthreads();

    int cg = tid & 15, ng = tid >> 4;
    int c0 = cg * 4, n0 = ng * 4;
    float acc[4][4];
    #pragma unroll
    for (int j = 0; j < 4; j++)
        #pragma unroll
        for (int cc = 0; cc < 4; cc++) acc[j][cc] = 0.f;

    #pragma unroll 2
    for (int k = 0; k < 128; k += 4) {
        float a[4][4];
        #pragma unroll
        for (int j = 0; j < 4; j++)
            *(float4*)a[j] = *(const float4*)&As[(n0 + j) * AS2 + k];
        #pragma unroll
        for (int kk = 0; kk < 4; kk++) {
            float4 b = *(const float4*)&Ws[(k + kk) * 64 + c0];
            float bb[4] = {b.x, b.y, b.z, b.w};
            #pragma unroll
            for (int j = 0; j < 4; j++) {
                float av = a[j][kk];
                #pragma unroll
                for (int cc = 0; cc < 4; cc++)
                    acc[j][cc] = fmaf(av, bb[cc], acc[j][cc]);
            }
        }
    }

    float al[4], be[4];
    #pragma unroll
    for (int cc = 0; cc < 4; cc++) {
        al[cc] = g_alpha2[layer][c0 + cc];
        be[cc] = g_beta2[layer][c0 + cc];
    }
    #pragma unroll
    for (int j = 0; j < 4; j++) {
        int node = m0 + n0 + j;
        if (node < NODES) {
            float o[4];
            #pragma unroll
            for (int cc = 0; cc < 4; cc++) {
                float v = fmaf(acc[j][cc], al[cc], be[cc]);
                o[cc] = relu ? fmaxf(v, 0.f) : v;
            }
            *(float4*)&g_h[node * DIMS + c0] = make_float4(o[0], o[1], o[2], o[3]);
        }
    }
}

// ---------------- global mean pool (atomic-free: binary search ranges) --------
__global__ void pool_kernel(float* __restrict__ out) {
    int g = blockIdx.x;
    int d = threadIdx.x;   // 64 threads
    int lo = 0, hi = NODES;
    while (lo < hi) { int mid = (lo + hi) >> 1; if (g_batI[mid] < g) lo = mid + 1; else hi = mid; }
    int start = lo;
    lo = start; hi = NODES;
    while (lo < hi) { int mid = (lo + hi) >> 1; if (g_batI[mid] < g + 1) lo = mid + 1; else hi = mid; }
    int end = lo;
    float s = 0.f;
    for (int n = start; n < end; n++) s += g_h[n * DIMS + d];
    float cnt = (float)(end - start);
    out[g * DIMS + d] = s / fmaxf(cnt, 1.0f);
}

// ---------------- launch ------------------------------------------------------
extern "C" void kernel_launch(void* const* d_in, const int* in_sizes, int n_in,
                              void* d_out, int out_size) {
    const float* x    = (const float*)d_in[0];
    const void*  ei   = d_in[1];
    const void*  bat  = d_in[2];
    const float* W1   = (const float*)d_in[3];
    const float* b1   = (const float*)d_in[4];
    const float* g1   = (const float*)d_in[5];
    const float* bt1  = (const float*)d_in[6];
    const float* m1   = (const float*)d_in[7];
    const float* v1   = (const float*)d_in[8];
    const float* W2   = (const float*)d_in[9];
    const float* b2   = (const float*)d_in[10];
    const float* g2   = (const float*)d_in[11];
    const float* bt2  = (const float*)d_in[12];
    const float* m2   = (const float*)d_in[13];
    const float* v2   = (const float*)d_in[14];
    float* out = (float*)d_out;

    cudaFuncSetAttribute(gemm1_kernel, cudaFuncAttributeMaxDynamicSharedMemorySize,
                         (64 * AS1 + 64 * 128) * 4);
    cudaFuncSetAttribute(gemm2_kernel, cudaFuncAttributeMaxDynamicSharedMemorySize,
                         (64 * AS2 + 128 * 64) * 4);

    // h <- x ; BN folding
    copy_x_kernel<<<(NODES * 16 + 255) / 256, 256>>>((const float4*)x);
    prep_kernel<<<NLAYER, 128>>>(b1, g1, bt1, m1, v1, b2, g2, bt2, m2, v2);

    // index dtype detect + convert + CSR build
    probe_kernel<<<1, 1>>>((const int*)ei);
    zero_deg_kernel<<<(NODES + 255) / 256, 256>>>();
    conv_edges_kernel<<<(EDGES + 255) / 256, 256>>>(ei);
    conv_batch_kernel<<<(NODES + 255) / 256, 256>>>(bat);
    scan1_kernel<<<SCAN_NB, SCAN_B>>>();
    scan2_kernel<<<1, 128>>>();
    scan3_kernel<<<SCAN_NB, SCAN_B>>>();
    fill_kernel<<<(EDGES + 255) / 256, 256>>>();

    int gemm_blocks = (NODES + 63) / 64;
    size_t smem1 = (size_t)(64 * AS1 + 64 * 128) * 4;
    size_t smem2 = (size_t)(64 * AS2 + 128 * 64) * 4;

    for (int l = 0; l < NLAYER; l++) {
        agg_kernel<<<(NODES * 32 + 255) / 256, 256>>>();
        gemm1_kernel<<<gemm_blocks, 256, smem1>>>(W1, l);
        gemm2_kernel<<<gemm_blocks, 256, smem2>>>(W2, l, (l != NLAYER - 1) ? 1 : 0);
    }

    pool_kernel<<<NGRAPH, 64>>>(out);
}